// round 7
// baseline (speedup 1.0000x reference)
#include <cuda_runtime.h>
#include <cuda_bf16.h>
#include <cstdint>
#include <cstddef>

#define B_   8
#define N_   8192
#define M_   2048
#define CIN  64
#define AST  136      // A row stride (bf16): 272B -> conflict-free frags
#define WST  72       // W row stride (bf16): 144B -> conflict-free frags

// smem byte offsets (total 110592 -> 2 CTAs/SM)
#define OFF_BIAS 0                        // 512 f32
#define OFF_PMAX 2048                     // 4 x 128 f32
#define OFF_AHI  4096                     // 128 x 136 bf16 = 34816
#define OFF_ALO  (OFF_AHI + 34816)
#define OFF_WHI  (OFF_ALO + 34816)        // 128 x 72 bf16 = 18432
#define OFF_WLO  (OFF_WHI + 18432)
#define SMEM_BYTES (OFF_WLO + 18432)      // 110592

__device__ float g_featT[(size_t)B_ * N_ * CIN];   // featT[b][n][c]

__device__ __forceinline__ void bsplit(float v, __nv_bfloat16& h, __nv_bfloat16& l) {
    h = __float2bfloat16(v);
    l = __float2bfloat16(v - __bfloat162float(h));
}
__device__ __forceinline__ uint32_t pk(__nv_bfloat16 a, __nv_bfloat16 b) {
    __nv_bfloat162 t(a, b);
    return *(uint32_t*)&t;
}
__device__ __forceinline__ void store4q(__nv_bfloat16* hiB, __nv_bfloat16* loB,
                                        int elemOff, const float* v) {
    __nv_bfloat16 h0,l0,h1,l1,h2,l2,h3,l3;
    bsplit(v[0], h0, l0); bsplit(v[1], h1, l1);
    bsplit(v[2], h2, l2); bsplit(v[3], h3, l3);
    uint2 hh; hh.x = pk(h0, h1); hh.y = pk(h2, h3);
    uint2 ll; ll.x = pk(l0, l1); ll.y = pk(l2, l3);
    *(uint2*)(hiB + elemOff) = hh;
    *(uint2*)(loB + elemOff) = ll;
}

__device__ __forceinline__ void mma_bf16(float c[4], const uint32_t a[4],
                                         uint32_t b0, uint32_t b1) {
    asm volatile(
        "mma.sync.aligned.m16n8k16.row.col.f32.bf16.bf16.f32 "
        "{%0,%1,%2,%3}, {%4,%5,%6,%7}, {%8,%9}, {%0,%1,%2,%3};"
        : "+f"(c[0]), "+f"(c[1]), "+f"(c[2]), "+f"(c[3])
        : "r"(a[0]), "r"(a[1]), "r"(a[2]), "r"(a[3]), "r"(b0), "r"(b1));
}

// One K-chunk of the m32 x n64 warp-tile GEMM (3-pass bf16 compensation).
// A read at global k = kbase + klocal; W buffer holds klocal in [0, KS*16).
template<int KS>
__device__ __forceinline__ void gemm_chunk(const __nv_bfloat16* __restrict__ sAhi,
                                           const __nv_bfloat16* __restrict__ sAlo,
                                           const __nv_bfloat16* __restrict__ sWhi,
                                           const __nv_bfloat16* __restrict__ sWlo,
                                           int kbase, int r0, int n0, int lane,
                                           float C[2][8][4])
{
    const int rq = lane >> 2, kq = (lane & 3) * 2;
    #pragma unroll 2
    for (int ks = 0; ks < KS; ks++) {
        const int kl = ks * 16 + kq;
        const int ka = kbase + kl;
        uint32_t ahi[2][4], alo[2][4];
        #pragma unroll
        for (int mt = 0; mt < 2; mt++) {
            const int ra = r0 + mt * 16 + rq;
            ahi[mt][0] = *(const uint32_t*)(sAhi + ra * AST + ka);
            ahi[mt][1] = *(const uint32_t*)(sAhi + (ra + 8) * AST + ka);
            ahi[mt][2] = *(const uint32_t*)(sAhi + ra * AST + ka + 8);
            ahi[mt][3] = *(const uint32_t*)(sAhi + (ra + 8) * AST + ka + 8);
            alo[mt][0] = *(const uint32_t*)(sAlo + ra * AST + ka);
            alo[mt][1] = *(const uint32_t*)(sAlo + (ra + 8) * AST + ka);
            alo[mt][2] = *(const uint32_t*)(sAlo + ra * AST + ka + 8);
            alo[mt][3] = *(const uint32_t*)(sAlo + (ra + 8) * AST + ka + 8);
        }
        #pragma unroll
        for (int j = 0; j < 8; j++) {
            const int n = n0 + j * 8 + rq;
            uint32_t bh0 = *(const uint32_t*)(sWhi + n * WST + kl);
            uint32_t bh1 = *(const uint32_t*)(sWhi + n * WST + kl + 8);
            uint32_t bl0 = *(const uint32_t*)(sWlo + n * WST + kl);
            uint32_t bl1 = *(const uint32_t*)(sWlo + n * WST + kl + 8);
            mma_bf16(C[0][j], ahi[0], bh0, bh1);
            mma_bf16(C[1][j], ahi[1], bh0, bh1);
            mma_bf16(C[0][j], ahi[0], bl0, bl1);
            mma_bf16(C[1][j], ahi[1], bl0, bl1);
            mma_bf16(C[0][j], alo[0], bh0, bh1);
            mma_bf16(C[1][j], alo[1], bh0, bh1);
        }
    }
}

__device__ __forceinline__ void zeroC(float C[2][8][4]) {
    #pragma unroll
    for (int mt = 0; mt < 2; mt++)
        #pragma unroll
        for (int j = 0; j < 8; j++)
            #pragma unroll
            for (int x = 0; x < 4; x++) C[mt][j][x] = 0.f;
}

// bias+relu -> bf16 hi/lo back into A (caller syncs before: WAR on A)
__device__ __forceinline__ void epi(const float C[2][8][4], const float* __restrict__ bias,
                                    int r0, int n0, int lane,
                                    __nv_bfloat16* __restrict__ sAhi,
                                    __nv_bfloat16* __restrict__ sAlo)
{
    const int rq = lane >> 2, q2 = (lane & 3) * 2;
    #pragma unroll
    for (int mt = 0; mt < 2; mt++) {
        const int ra = r0 + mt * 16 + rq;
        #pragma unroll
        for (int j = 0; j < 8; j++) {
            const int c0 = n0 + j * 8 + q2;
            const float bb0 = bias[c0], bb1 = bias[c0 + 1];
            float v0 = fmaxf(C[mt][j][0] + bb0, 0.f);
            float v1 = fmaxf(C[mt][j][1] + bb1, 0.f);
            float v2 = fmaxf(C[mt][j][2] + bb0, 0.f);
            float v3 = fmaxf(C[mt][j][3] + bb1, 0.f);
            __nv_bfloat16 h, l; __nv_bfloat162 hh, ll;
            bsplit(v0, h, l); hh.x = h; ll.x = l;
            bsplit(v1, h, l); hh.y = h; ll.y = l;
            *(__nv_bfloat162*)(sAhi + ra * AST + c0) = hh;
            *(__nv_bfloat162*)(sAlo + ra * AST + c0) = ll;
            bsplit(v2, h, l); hh.x = h; ll.x = l;
            bsplit(v3, h, l); hh.y = h; ll.y = l;
            *(__nv_bfloat162*)(sAhi + (ra + 8) * AST + c0) = hh;
            *(__nv_bfloat162*)(sAlo + (ra + 8) * AST + c0) = ll;
        }
    }
}

// stage W[kglobal][coloff+n] for kglobal in [kbase, kbase+kspan) -> [n][klocal]
__device__ __forceinline__ void stageW(const float* __restrict__ W, int ld, int coloff,
                                       int kbase, int kspan, int kreal,
                                       __nv_bfloat16* __restrict__ wHi,
                                       __nv_bfloat16* __restrict__ wLo, int tid)
{
    const int n = tid & 127;
    const int half = tid >> 7;
    const int ks2 = kspan >> 1;
    #pragma unroll 1
    for (int kl = half * ks2; kl < (half + 1) * ks2; kl += 4) {
        float v[4];
        #pragma unroll
        for (int j = 0; j < 4; j++) {
            const int kg = kbase + kl + j;
            v[j] = (kg < kreal) ? __ldg(W + (size_t)kg * ld + coloff + n) : 0.f;
        }
        store4q(wHi, wLo, n * WST + kl, v);
    }
}

// ---------------- feature transpose [C][N] -> [N][C] ----------------
__global__ __launch_bounds__(256) void tr_kernel(const float* __restrict__ feat) {
    __shared__ float t[64][65];
    const int b  = blockIdx.x >> 7;
    const int n0 = (blockIdx.x & 127) << 6;
    const int tid = threadIdx.x;
    const float* fb = feat + (size_t)b * CIN * N_;
    for (int i = tid; i < 64 * 64; i += 256) {
        int c = i >> 6, nj = i & 63;
        t[c][nj] = fb[(size_t)c * N_ + n0 + nj];
    }
    __syncthreads();
    const int nj = tid >> 2, cq = (tid & 3) * 16;
    float* drow = g_featT + ((size_t)b * N_ + n0 + nj) * CIN + cq;
    #pragma unroll
    for (int q = 0; q < 16; q += 4) {
        float4 v = make_float4(t[cq + q][nj], t[cq + q + 1][nj],
                               t[cq + q + 2][nj], t[cq + q + 3][nj]);
        *(float4*)(drow + q) = v;
    }
}

// ---------------- main: 128 rows (4 neighborhoods) per CTA, 2 CTAs/SM ----------------
__global__ __launch_bounds__(256, 2)
void ps_mma3(const float* __restrict__ xyz, const float* __restrict__ feat,
             const int* __restrict__ nbr, const int* __restrict__ anc,
             const float* __restrict__ W1, const float* __restrict__ b1,
             const float* __restrict__ W2, const float* __restrict__ b2,
             const float* __restrict__ W3, const float* __restrict__ b3,
             float* __restrict__ out)
{
    extern __shared__ char smem[];
    float* bias = (float*)(smem + OFF_BIAS);
    float* pmax = (float*)(smem + OFF_PMAX);
    __nv_bfloat16* sAhi = (__nv_bfloat16*)(smem + OFF_AHI);
    __nv_bfloat16* sAlo = (__nv_bfloat16*)(smem + OFF_ALO);
    __nv_bfloat16* sWhi = (__nv_bfloat16*)(smem + OFF_WHI);
    __nv_bfloat16* sWlo = (__nv_bfloat16*)(smem + OFF_WLO);

    const int tid = threadIdx.x, lane = tid & 31, w = tid >> 5;
    const int ct = blockIdx.x, b = ct >> 9;
    const int m0 = (ct & 511) << 2;       // 4 anchors per CTA

    for (int i = tid; i < 512; i += 256)
        bias[i] = (i < 128) ? b1[i] : (i < 256) ? b2[i - 128] : b3[i - 256];

    // ---- gather: rows [128][80] = [rel_xyz(3)|feat(64)|0..], 2 threads/row ----
    {
        const int r = tid >> 1, h = tid & 1;
        const int m = m0 + (r >> 5), k = r & 31;
        const int n = nbr[(b * M_ + m) * 32 + k];
        const int a = anc[b * M_ + m];
        const float* xb = xyz + (size_t)b * N_ * 3;
        const float* ft = g_featT + ((size_t)b * N_ + n) * CIN;
        float xr[3];
        if (h == 0) {
            xr[0] = xb[n * 3 + 0] - xb[a * 3 + 0];
            xr[1] = xb[n * 3 + 1] - xb[a * 3 + 1];
            xr[2] = xb[n * 3 + 2] - xb[a * 3 + 2];
        }
        #pragma unroll 1
        for (int cb = h * 4; cb < 80; cb += 8) {
            float v[4];
            #pragma unroll
            for (int j = 0; j < 4; j++) {
                const int c = cb + j;
                v[j] = (c < 3) ? xr[c] : (c < 67) ? __ldg(ft + (c - 3)) : 0.f;
            }
            store4q(sAhi, sAlo, r * AST + cb, v);
        }
    }

    const int rg = w & 3;                 // row group == neighborhood
    const int r0 = rg * 32;
    const int n0 = (w >> 2) * 64;         // col half
    float C[2][8][4];

    // ---- layer 1: K=80 (67 real) ----
    stageW(W1, 128, 0, 0, 64, 67, sWhi, sWlo, tid);
    zeroC(C);
    __syncthreads();
    gemm_chunk<4>(sAhi, sAlo, sWhi, sWlo, 0, r0, n0, lane, C);
    __syncthreads();
    stageW(W1, 128, 0, 64, 16, 67, sWhi, sWlo, tid);
    __syncthreads();
    gemm_chunk<1>(sAhi, sAlo, sWhi, sWlo, 64, r0, n0, lane, C);
    __syncthreads();
    epi(C, bias, r0, n0, lane, sAhi, sAlo);
    __syncthreads();

    // ---- layer 2: K=128 ----
    stageW(W2, 128, 0, 0, 64, 128, sWhi, sWlo, tid);
    zeroC(C);
    __syncthreads();
    gemm_chunk<4>(sAhi, sAlo, sWhi, sWlo, 0, r0, n0, lane, C);
    __syncthreads();
    stageW(W2, 128, 0, 64, 64, 128, sWhi, sWlo, tid);
    __syncthreads();
    gemm_chunk<4>(sAhi, sAlo, sWhi, sWlo, 64, r0, n0, lane, C);
    __syncthreads();
    epi(C, bias + 128, r0, n0, lane, sAhi, sAlo);
    __syncthreads();

    // ---- layer 3: two 128-col halves + in-warp maxpool ----
    #pragma unroll 1
    for (int h3 = 0; h3 < 2; h3++) {
        stageW(W3, 256, h3 * 128, 0, 64, 128, sWhi, sWlo, tid);
        zeroC(C);
        __syncthreads();
        gemm_chunk<4>(sAhi, sAlo, sWhi, sWlo, 0, r0, n0, lane, C);
        __syncthreads();
        stageW(W3, 256, h3 * 128, 64, 64, 128, sWhi, sWlo, tid);
        __syncthreads();
        gemm_chunk<4>(sAhi, sAlo, sWhi, sWlo, 64, r0, n0, lane, C);

        // warp tile covers one full neighborhood (32 rows) x 64 cols -> pool in-warp
        const int q2 = (lane & 3) * 2;
        #pragma unroll
        for (int j = 0; j < 8; j++) {
            const int c0 = n0 + j * 8 + q2;
            const float bb0 = bias[256 + h3 * 128 + c0];
            const float bb1 = bias[256 + h3 * 128 + c0 + 1];
            float v0 = fmaxf(fmaxf(C[0][j][0], C[0][j][2]),
                             fmaxf(C[1][j][0], C[1][j][2]));
            float v1 = fmaxf(fmaxf(C[0][j][1], C[0][j][3]),
                             fmaxf(C[1][j][1], C[1][j][3]));
            v0 = fmaxf(v0 + bb0, 0.f);
            v1 = fmaxf(v1 + bb1, 0.f);
            #pragma unroll
            for (int s = 4; s < 32; s <<= 1) {
                v0 = fmaxf(v0, __shfl_xor_sync(0xFFFFFFFFu, v0, s));
                v1 = fmaxf(v1, __shfl_xor_sync(0xFFFFFFFFu, v1, s));
            }
            if (lane < 4) {
                pmax[rg * 128 + c0]     = v0;
                pmax[rg * 128 + c0 + 1] = v1;
            }
        }
        __syncthreads();

        // coalesced out: 4 consecutive m per col
        if (tid < 128) {
            const int col = tid;
            float4 f = make_float4(pmax[0 * 128 + col], pmax[1 * 128 + col],
                                   pmax[2 * 128 + col], pmax[3 * 128 + col]);
            *(float4*)(out + ((size_t)(b * 256 + h3 * 128 + col)) * M_ + m0) = f;
        }
        __syncthreads();
    }
}

extern "C" void kernel_launch(void* const* d_in, const int* in_sizes, int n_in,
                              void* d_out, int out_size)
{
    const float* xyz  = (const float*)d_in[0];
    const float* feat = (const float*)d_in[1];
    const int*   nbr  = (const int*)d_in[2];
    const int*   anc  = (const int*)d_in[3];
    const float* W1   = (const float*)d_in[4];
    const float* b1   = (const float*)d_in[5];
    const float* W2   = (const float*)d_in[6];
    const float* b2   = (const float*)d_in[7];
    const float* W3   = (const float*)d_in[8];
    const float* b3   = (const float*)d_in[9];
    float* out = (float*)d_out;

    tr_kernel<<<B_ * (N_ / 64), 256>>>(feat);
    cudaFuncSetAttribute(ps_mma3, cudaFuncAttributeMaxDynamicSharedMemorySize, SMEM_BYTES);
    ps_mma3<<<4096, 256, SMEM_BYTES>>>(xyz, feat, nbr, anc, W1, b1, W2, b2, W3, b3, out);
}